// round 15
// baseline (speedup 1.0000x reference)
#include <cuda_runtime.h>
#include <cuda_bf16.h>
#include <math.h>
#include <stdint.h>

#define NCL 10
#define DD 64
#define TPB1 512
#define CLN 8
#define SPB 4          // slots per block in phase 2
#define NBLK2 (4096 / SPB)

// final cluster centers from the iterative part
__device__ float g_cc[NCL * DD];

// ---------------- helpers ----------------

__device__ __forceinline__ float fast_sigmoid(float x) {
    return 1.f / (1.f + __expf(-x));
}
__device__ __forceinline__ float fast_tanh(float x) {
    return 1.f - 2.f / (1.f + __expf(2.f * x));
}

__device__ __forceinline__ void cp_async16(float* smem_dst, const float* gsrc) {
    unsigned d = (unsigned)__cvta_generic_to_shared(smem_dst);
    asm volatile("cp.async.cg.shared.global [%0], [%1], 16;\n" :: "r"(d), "l"(gsrc));
}

__device__ __forceinline__ uint32_t smem_u32(const void* p) {
    uint32_t a;
    asm("{ .reg .u64 t; cvta.to.shared.u64 t, %1; cvt.u32.u64 %0, t; }" : "=r"(a) : "l"(p));
    return a;
}
__device__ __forceinline__ uint32_t mapa_rank(uint32_t laddr, int rank) {
    uint32_t ra;
    asm("mapa.shared::cluster.u32 %0, %1, %2;" : "=r"(ra) : "r"(laddr), "r"(rank));
    return ra;
}
__device__ __forceinline__ void st_cluster_f32(uint32_t addr, float v) {
    asm volatile("st.shared::cluster.f32 [%0], %1;" :: "r"(addr), "f"(v));
}
#define CSYNC() do { \
    asm volatile("barrier.cluster.arrive.aligned;" ::: "memory"); \
    asm volatile("barrier.cluster.wait.aligned;" ::: "memory"); } while (0)

// XOR swizzle: (r, c) -> r*L + (c ^ ((r<<2) & (L-4))).
__device__ __forceinline__ void stage_w(const float* __restrict__ g, float* __restrict__ s,
                                        int R, int L, int tid, int T) {
    int total4 = (R * L) >> 2;
    for (int e4 = tid; e4 < total4; e4 += T) {
        int e = e4 << 2;
        int r = e / L;
        int c = e & (L - 1);
        float4 v = *reinterpret_cast<const float4*>(g + e);
        *reinterpret_cast<float4*>(s + r * L + (c ^ ((r << 2) & (L - 4)))) = v;
    }
}

__device__ __forceinline__ void stage_w_async(const float* __restrict__ g, float* __restrict__ s,
                                              int R, int L, int tid, int T) {
    int total4 = (R * L) >> 2;
    for (int e4 = tid; e4 < total4; e4 += T) {
        int e = e4 << 2;
        int r = e / L;
        int c = e & (L - 1);
        cp_async16(s + r * L + (c ^ ((r << 2) & (L - 4))), g + e);
    }
}

// scalar gemm: acc[n] = sum_{c in [c0,c0+nc)} W[r][c]*act[n*L+c]
__device__ __forceinline__ void gemm_sc(const float* __restrict__ Wsm,
                                        const float* __restrict__ act,
                                        int r, int L, int c0, int nc, float* acc) {
#pragma unroll
    for (int n = 0; n < NCL; n++) acc[n] = 0.f;
    const int sw = (r << 2) & (L - 4);
    const float* wrow = Wsm + r * L;
#pragma unroll 4
    for (int c = c0; c < c0 + nc; c += 4) {
        float4 w = *reinterpret_cast<const float4*>(wrow + (c ^ sw));
#pragma unroll
        for (int n = 0; n < NCL; n++) {
            float4 a = *reinterpret_cast<const float4*>(act + n * L + c);
            acc[n] = fmaf(w.x, a.x, acc[n]);
            acc[n] = fmaf(w.y, a.y, acc[n]);
            acc[n] = fmaf(w.z, a.z, acc[n]);
            acc[n] = fmaf(w.w, a.w, acc[n]);
        }
    }
}

// ---------------- phase 1: iterative slot attention, 8-CTA cluster (R14 proven) ----------------

__global__ void __launch_bounds__(TPB1) __cluster_dims__(CLN, 1, 1) phase1_kernel(
    const float* __restrict__ cc0,
    const float* __restrict__ Wk, const float* __restrict__ bk,
    const float* __restrict__ Wq, const float* __restrict__ bq,
    const float* __restrict__ Wv, const float* __restrict__ bv,
    const float* __restrict__ ccg, const float* __restrict__ ccb,
    const float* __restrict__ Wih, const float* __restrict__ Whh,
    const float* __restrict__ bih, const float* __restrict__ bhh,
    const float* __restrict__ g_lng, const float* __restrict__ g_lnb,
    const float* __restrict__ W1, const float* __restrict__ b1,
    const float* __restrict__ W2, const float* __restrict__ b2)
{
    extern __shared__ float sm[];
    float* Wq_s   = sm;                 // 4096
    float* Wih_s  = Wq_s + 4096;        // 12288
    float* Whh_s  = Wih_s + 12288;      // 12288
    float* W1_s   = Whh_s + 12288;      // 8192 (Wk during init)
    float* W2_s   = W1_s + 8192;        // 8192 (Wv during init)
    float* cc_s   = W2_s + 8192;        // 640
    float* ccp_s  = cc_s + 640;         // 640
    float* kk_s   = ccp_s + 640;        // 640
    float* lnx_s  = kk_s + 640;         // 640
    float* q_s    = lnx_s + 640;        // 640
    float* VW_s   = q_s + 640;          // 1920 ([m][192])
    float* gh_s   = VW_s + 1920;        // 1920 ([n][192])
    float* hh_s   = gh_s + 1920;        // 1280 ([n][128]); aliases vv during init
    float* attn_s = hh_s + 1280;        // 112 (100 used)
    float* mv_s   = attn_s + 112;       // 32 (20 used)
    float* vv_s   = hh_s;               // alias

    const int tid  = threadIdx.x;
    const int lane = tid & 31;
    const int wid  = tid >> 5;
    uint32_t rank;
    asm("mov.u32 %0, %%cluster_ctarank;" : "=r"(rank));

    const uint32_t kk_u = smem_u32(kk_s);
    const uint32_t vv_u = smem_u32(vv_s);
    const uint32_t q_u  = smem_u32(q_s);
    const uint32_t gh_u = smem_u32(gh_s);
    const uint32_t vw_u = smem_u32(VW_s);
    const uint32_t cc_u = smem_u32(cc_s);
    const uint32_t hh_u = smem_u32(hh_s);

    stage_w_async(Wih, Wih_s, 192, 64, tid, TPB1);
    stage_w_async(Whh, Whh_s, 192, 64, tid, TPB1);
    asm volatile("cp.async.commit_group;\n" ::: "memory");   // G0

    stage_w(Wq, Wq_s, 64, 64, tid, TPB1);
    stage_w(Wk, W1_s, 64, 64, tid, TPB1);
    stage_w(Wv, W2_s, 64, 64, tid, TPB1);
    if (tid < 160) *reinterpret_cast<float4*>(cc_s + tid * 4) =
        *reinterpret_cast<const float4*>(cc0 + tid * 4);
    __syncthreads();

    // k, v : 16 rows per CTA, splitk4 -> tid<64
    if (tid < 64) {
        int rid = tid >> 2, kp = tid & 3;
        int grow = rank * 16 + rid;
        float acc[NCL];
        const float* Wm = (grow < 64) ? W1_s : W2_s;
        int row = grow & 63;
        gemm_sc(Wm, cc_s, row, 64, kp * 16, 16, acc);
#pragma unroll
        for (int n = 0; n < NCL; n++) {
            acc[n] += __shfl_xor_sync(0xffffffffu, acc[n], 1);
            acc[n] += __shfl_xor_sync(0xffffffffu, acc[n], 2);
        }
        if (kp == 0) {
            float b = (grow < 64) ? bk[row] : bv[row];
            uint32_t base_u = (grow < 64) ? kk_u : vv_u;
            float vals[NCL];
#pragma unroll
            for (int n = 0; n < NCL; n++) vals[n] = acc[n] + b;
            for (int pr = 0; pr < CLN; pr++) {
                uint32_t b0 = mapa_rank(base_u, pr);
#pragma unroll
                for (int n = 0; n < NCL; n++)
                    st_cluster_f32(b0 + (uint32_t)(n * 64 + row) * 4u, vals[n]);
            }
        }
    }
    CSYNC();

    stage_w_async(W1, W1_s, 128, 64, tid, TPB1);
    stage_w_async(W2, W2_s, 64, 128, tid, TPB1);
    asm volatile("cp.async.commit_group;\n" ::: "memory");   // G1
    asm volatile("cp.async.wait_group 1;\n" ::: "memory");
    __syncthreads();

    // VW: 24 rows per CTA, splitk4 -> tid<96
    if (tid < 96) {
        int rid = tid >> 2, kp = tid & 3;
        int grow = rank * 24 + rid;
        float acc[NCL];
        gemm_sc(Wih_s, vv_s, grow, 64, kp * 16, 16, acc);
#pragma unroll
        for (int n = 0; n < NCL; n++) {
            acc[n] += __shfl_xor_sync(0xffffffffu, acc[n], 1);
            acc[n] += __shfl_xor_sync(0xffffffffu, acc[n], 2);
        }
        if (kp == 0) {
            for (int pr = 0; pr < CLN; pr++) {
                uint32_t b0 = mapa_rank(vw_u, pr);
#pragma unroll
                for (int n = 0; n < NCL; n++)
                    st_cluster_f32(b0 + (uint32_t)(n * 192 + grow) * 4u, acc[n]);
            }
        }
    }
    asm volatile("cp.async.wait_group 0;\n" ::: "memory");
    CSYNC();

    for (int it = 0; it < 3; ++it) {
        ccp_s[tid] = cc_s[tid];
        if (tid < 128) ccp_s[512 + tid] = cc_s[512 + tid];
        if (wid < NCL) {
            float x0 = cc_s[wid * 64 + lane * 2];
            float x1 = cc_s[wid * 64 + lane * 2 + 1];
            float s = x0 + x1, q2 = x0 * x0 + x1 * x1;
#pragma unroll
            for (int o = 16; o; o >>= 1) {
                s  += __shfl_xor_sync(0xffffffffu, s, o);
                q2 += __shfl_xor_sync(0xffffffffu, q2, o);
            }
            if (lane == 0) {
                float m = s * (1.f / 64.f);
                mv_s[2 * wid] = m;
                mv_s[2 * wid + 1] = rsqrtf(q2 * (1.f / 64.f) - m * m + 1e-5f);
            }
        }
        __syncthreads();
        {
            int e = tid, n = e >> 6, i = e & 63;
            lnx_s[e] = (cc_s[e] - mv_s[2 * n]) * mv_s[2 * n + 1] * ccg[i] + ccb[i];
            if (tid < 128) {
                e = 512 + tid; n = e >> 6; i = e & 63;
                lnx_s[e] = (cc_s[e] - mv_s[2 * n]) * mv_s[2 * n + 1] * ccg[i] + ccb[i];
            }
        }
        __syncthreads();

        // stage A: 32 rows per CTA, splitk4 -> tid<128
        if (tid < 128) {
            int rid = tid >> 2, kp = tid & 3;
            int grow = rank * 32 + rid;
            float acc[NCL];
            if (grow < 64) gemm_sc(Wq_s, lnx_s, grow, 64, kp * 16, 16, acc);
            else           gemm_sc(Whh_s, ccp_s, grow - 64, 64, kp * 16, 16, acc);
#pragma unroll
            for (int n = 0; n < NCL; n++) {
                acc[n] += __shfl_xor_sync(0xffffffffu, acc[n], 1);
                acc[n] += __shfl_xor_sync(0xffffffffu, acc[n], 2);
            }
            if (kp == 0) {
                float vals[NCL];
                if (grow < 64) {
                    float b = bq[grow];
#pragma unroll
                    for (int n = 0; n < NCL; n++) vals[n] = acc[n] + b;
                    for (int pr = 0; pr < CLN; pr++) {
                        uint32_t b0 = mapa_rank(q_u, pr);
#pragma unroll
                        for (int n = 0; n < NCL; n++)
                            st_cluster_f32(b0 + (uint32_t)(n * 64 + grow) * 4u, vals[n]);
                    }
                } else {
                    int r = grow - 64;
                    float b = bhh[r];
#pragma unroll
                    for (int n = 0; n < NCL; n++) vals[n] = acc[n] + b;
                    for (int pr = 0; pr < CLN; pr++) {
                        uint32_t b0 = mapa_rank(gh_u, pr);
#pragma unroll
                        for (int n = 0; n < NCL; n++)
                            st_cluster_f32(b0 + (uint32_t)(n * 192 + r) * 4u, vals[n]);
                    }
                }
            }
        }
        CSYNC();

        // replicated: logits, softmax, renorm
        {
            int nm = tid >> 2; if (nm > 99) nm = 99;
            int kp = tid & 3;
            int n = nm / 10, m = nm % 10;
            float s = 0.f;
            int c0 = kp * 16;
#pragma unroll
            for (int j = 0; j < 16; j++)
                s = fmaf(kk_s[n * 64 + c0 + j], q_s[m * 64 + c0 + j], s);
            s += __shfl_xor_sync(0xffffffffu, s, 1);
            s += __shfl_xor_sync(0xffffffffu, s, 2);
            if (tid < 400 && kp == 0) attn_s[n * 10 + m] = s * 0.125f;
        }
        __syncthreads();
        if (tid < NCL) {
            int m = tid;
            float a[NCL], mx = -1e30f;
#pragma unroll
            for (int n = 0; n < NCL; n++) { a[n] = attn_s[n * 10 + m]; mx = fmaxf(mx, a[n]); }
            float ss = 0.f;
#pragma unroll
            for (int n = 0; n < NCL; n++) { a[n] = __expf(a[n] - mx); ss += a[n]; }
            float inv = 1.f / ss;
#pragma unroll
            for (int n = 0; n < NCL; n++) attn_s[n * 10 + m] = a[n] * inv + 1e-8f;
        }
        __syncthreads();
        if (tid < NCL) {
            int n = tid;
            float ss = 0.f;
#pragma unroll
            for (int m = 0; m < NCL; m++) ss += attn_s[n * 10 + m];
            float inv = 1.f / ss;
#pragma unroll
            for (int m = 0; m < NCL; m++) attn_s[n * 10 + m] *= inv;
        }
        __syncthreads();

        // GRU: 80 elements per CTA
        if (tid < 80) {
            int e = rank * 80 + tid;
            int n = e >> 6, i = e & 63;
            float gi0 = bih[i], gi1 = bih[64 + i], gi2 = bih[128 + i];
#pragma unroll
            for (int m = 0; m < NCL; m++) {
                float a = attn_s[n * 10 + m];
                const float* vw = VW_s + m * 192;
                gi0 = fmaf(a, vw[i], gi0);
                gi1 = fmaf(a, vw[64 + i], gi1);
                gi2 = fmaf(a, vw[128 + i], gi2);
            }
            float h0 = gh_s[n * 192 + i];
            float h1 = gh_s[n * 192 + 64 + i];
            float h2 = gh_s[n * 192 + 128 + i];
            float r = fast_sigmoid(gi0 + h0);
            float z = fast_sigmoid(gi1 + h1);
            float nn = fast_tanh(gi2 + r * h2);
            float v = (1.f - z) * nn + z * ccp_s[e];
            for (int pr = 0; pr < CLN; pr++)
                st_cluster_f32(mapa_rank(cc_u, pr) + (uint32_t)e * 4u, v);
        }
        CSYNC();

        // LN2 stats + lnx
        if (wid < NCL) {
            float x0 = cc_s[wid * 64 + lane * 2];
            float x1 = cc_s[wid * 64 + lane * 2 + 1];
            float s = x0 + x1, q2 = x0 * x0 + x1 * x1;
#pragma unroll
            for (int o = 16; o; o >>= 1) {
                s  += __shfl_xor_sync(0xffffffffu, s, o);
                q2 += __shfl_xor_sync(0xffffffffu, q2, o);
            }
            if (lane == 0) {
                float m = s * (1.f / 64.f);
                mv_s[2 * wid] = m;
                mv_s[2 * wid + 1] = rsqrtf(q2 * (1.f / 64.f) - m * m + 1e-5f);
            }
        }
        __syncthreads();
        {
            int e = tid, n = e >> 6, i = e & 63;
            lnx_s[e] = (cc_s[e] - mv_s[2 * n]) * mv_s[2 * n + 1] * g_lng[i] + g_lnb[i];
            if (tid < 128) {
                e = 512 + tid; n = e >> 6; i = e & 63;
                lnx_s[e] = (cc_s[e] - mv_s[2 * n]) * mv_s[2 * n + 1] * g_lng[i] + g_lnb[i];
            }
        }
        __syncthreads();

        // MLP1: 16 rows per CTA, splitk4 -> tid<64
        if (tid < 64) {
            int rid = tid >> 2, kp = tid & 3;
            int grow = rank * 16 + rid;
            float acc[NCL];
            gemm_sc(W1_s, lnx_s, grow, 64, kp * 16, 16, acc);
#pragma unroll
            for (int n = 0; n < NCL; n++) {
                acc[n] += __shfl_xor_sync(0xffffffffu, acc[n], 1);
                acc[n] += __shfl_xor_sync(0xffffffffu, acc[n], 2);
            }
            if (kp == 0) {
                float b = b1[grow];
                float vals[NCL];
#pragma unroll
                for (int n = 0; n < NCL; n++) vals[n] = fmaxf(acc[n] + b, 0.f);
                for (int pr = 0; pr < CLN; pr++) {
                    uint32_t b0 = mapa_rank(hh_u, pr);
#pragma unroll
                    for (int n = 0; n < NCL; n++)
                        st_cluster_f32(b0 + (uint32_t)(n * 128 + grow) * 4u, vals[n]);
                }
            }
        }
        CSYNC();

        // MLP2 + residual: 8 rows per CTA, splitk8 -> tid<64
        if (tid < 64) {
            int rid = tid >> 3, kp = tid & 7;
            int grow = rank * 8 + rid;
            float acc[NCL];
            gemm_sc(W2_s, hh_s, grow, 128, kp * 16, 16, acc);
#pragma unroll
            for (int n = 0; n < NCL; n++) {
                acc[n] += __shfl_xor_sync(0xffffffffu, acc[n], 1);
                acc[n] += __shfl_xor_sync(0xffffffffu, acc[n], 2);
                acc[n] += __shfl_xor_sync(0xffffffffu, acc[n], 4);
            }
            if (kp == 0) {
                float b = b2[grow];
                float vals[NCL];
#pragma unroll
                for (int n = 0; n < NCL; n++)
                    vals[n] = cc_s[n * 64 + grow] + acc[n] + b;
                for (int pr = 0; pr < CLN; pr++) {
                    uint32_t b0 = mapa_rank(cc_u, pr);
#pragma unroll
                    for (int n = 0; n < NCL; n++)
                        st_cluster_f32(b0 + (uint32_t)(n * 64 + grow) * 4u, vals[n]);
                }
            }
        }
        CSYNC();
    }

    if (rank == 0) {
        g_cc[tid] = cc_s[tid];
        if (tid < 128) g_cc[512 + tid] = cc_s[512 + tid];
    }
}

// ---------------- kernel 2: per-slot MLP + max — 4 slots/block, 2-deep weight pipeline ----------------
// Each block processes SPB=4 consecutive slots. Weights for slot s+1/s+2 stream via
// cp.async while slot s computes -> DRAM and FMA phases overlap continuously.
// smem: 2 stage buffers x (Wa|Wb = 8192 floats) + cc + hsm = ~70.7 KB -> 3 blocks/SM.

__global__ void __launch_bounds__(64) slot_kernel(
    const float* __restrict__ Wa, const float* __restrict__ ba,
    const float* __restrict__ Wb, const float* __restrict__ bb,
    float* __restrict__ out)
{
    extern __shared__ float smem2[];
    float* bufW = smem2;            // [2][8192]: stage s&1, first 4096 = Wa, next = Wb
    float* cc2  = bufW + 16384;     // 640
    float* hsm  = cc2 + 640;        // 640

    const int t = threadIdx.x;
    const int slot0 = blockIdx.x * SPB;

    // issue weights for slot (swizzled per-4096 region) into stage buffer
    auto issue_slot = [&](int s, int stage) {
        const float* wa = Wa + (size_t)(slot0 + s) * 4096;
        const float* wb = Wb + (size_t)(slot0 + s) * 4096;
        float* dstA = bufW + stage * 8192;
        float* dstB = dstA + 4096;
#pragma unroll
        for (int k = 0; k < 16; ++k) {
            int e = (t + 64 * k) * 4;
            int r = e >> 6, c = e & 63;
            int so = r * 64 + (c ^ ((r << 2) & 60));
            cp_async16(dstA + so, wa + e);
            cp_async16(dstB + so, wb + e);
        }
        asm volatile("cp.async.commit_group;\n" ::: "memory");
    };

    issue_slot(0, 0);
    issue_slot(1, 1);

    for (int e = t; e < 640; e += 64) cc2[e] = g_cc[e];

#pragma unroll
    for (int s = 0; s < SPB; ++s) {
        // groups committed so far: 2 + min(s,2); need group s done
        if (s < SPB - 1) asm volatile("cp.async.wait_group 1;\n" ::: "memory");
        else             asm volatile("cp.async.wait_group 0;\n" ::: "memory");
        __syncthreads();

        const float* WA = bufW + (s & 1) * 8192;
        const float* WB = WA + 4096;
        const int slot = slot0 + s;

        float acc[NCL];
        // layer 1
        gemm_sc(WA, cc2, t, 64, 0, 64, acc);
        {
            float b = ba[slot * 64 + t];
#pragma unroll
            for (int n = 0; n < NCL; n++) hsm[n * 64 + t] = fmaxf(acc[n] + b, 0.f);
        }
        __syncthreads();

        // layer 2 + max
        gemm_sc(WB, hsm, t, 64, 0, 64, acc);
        float b = bb[slot * 64 + t];
        float m = -3.4e38f;
#pragma unroll
        for (int n = 0; n < NCL; n++) m = fmaxf(m, acc[n] + b);
        out[slot * 64 + t] = m;
        __syncthreads();   // everyone done reading bufW[s&1] and hsm

        if (s + 2 < SPB) issue_slot(s + 2, s & 1);
    }
}

// ---------------- launch ----------------

extern "C" void kernel_launch(void* const* d_in, const int* in_sizes, int n_in,
                              void* d_out, int out_size) {
    const float* cc0 = (const float*)d_in[0];
    const float* Wk  = (const float*)d_in[1];
    const float* bk  = (const float*)d_in[2];
    const float* Wq  = (const float*)d_in[3];
    const float* bq  = (const float*)d_in[4];
    const float* Wv  = (const float*)d_in[5];
    const float* bv  = (const float*)d_in[6];
    const float* ccg = (const float*)d_in[7];
    const float* ccb = (const float*)d_in[8];
    const float* Wih = (const float*)d_in[9];
    const float* Whh = (const float*)d_in[10];
    const float* bih = (const float*)d_in[11];
    const float* bhh = (const float*)d_in[12];
    const float* lng = (const float*)d_in[13];
    const float* lnb = (const float*)d_in[14];
    const float* W1  = (const float*)d_in[15];
    const float* b1  = (const float*)d_in[16];
    const float* W2  = (const float*)d_in[17];
    const float* b2  = (const float*)d_in[18];
    const float* Wa  = (const float*)d_in[19];
    const float* ba  = (const float*)d_in[20];
    const float* Wb  = (const float*)d_in[21];
    const float* bb  = (const float*)d_in[22];
    float* out = (float*)d_out;

    constexpr int SMEM1 = 53520 * 4;                  // 214,080 B
    constexpr int SMEM2 = (16384 + 640 + 640) * 4;    // 70,656 B
    cudaFuncSetAttribute(phase1_kernel, cudaFuncAttributeMaxDynamicSharedMemorySize, SMEM1);
    cudaFuncSetAttribute(slot_kernel, cudaFuncAttributeMaxDynamicSharedMemorySize, SMEM2);

    phase1_kernel<<<CLN, TPB1, SMEM1>>>(cc0, Wk, bk, Wq, bq, Wv, bv, ccg, ccb,
                                        Wih, Whh, bih, bhh, lng, lnb, W1, b1, W2, b2);
    slot_kernel<<<NBLK2, 64, SMEM2>>>(Wa, ba, Wb, bb, out);
}

// round 17
// speedup vs baseline: 1.2410x; 1.2410x over previous
#include <cuda_runtime.h>
#include <cuda_bf16.h>
#include <math.h>
#include <stdint.h>

#define NCL 10
#define DD 64
#define TPB1 512
#define CLN 8

// final cluster centers from the iterative part
__device__ float g_cc[NCL * DD];

// ---------------- helpers ----------------

__device__ __forceinline__ float fast_sigmoid(float x) {
    return 1.f / (1.f + __expf(-x));
}
__device__ __forceinline__ float fast_tanh(float x) {
    return 1.f - 2.f / (1.f + __expf(2.f * x));
}

__device__ __forceinline__ void cp_async16(float* smem_dst, const float* gsrc) {
    unsigned d = (unsigned)__cvta_generic_to_shared(smem_dst);
    asm volatile("cp.async.cg.shared.global [%0], [%1], 16;\n" :: "r"(d), "l"(gsrc));
}

__device__ __forceinline__ uint32_t smem_u32(const void* p) {
    uint32_t a;
    asm("{ .reg .u64 t; cvta.to.shared.u64 t, %1; cvt.u32.u64 %0, t; }" : "=r"(a) : "l"(p));
    return a;
}
__device__ __forceinline__ uint32_t mapa_rank(uint32_t laddr, int rank) {
    uint32_t ra;
    asm("mapa.shared::cluster.u32 %0, %1, %2;" : "=r"(ra) : "r"(laddr), "r"(rank));
    return ra;
}
__device__ __forceinline__ void st_cluster_f32(uint32_t addr, float v) {
    asm volatile("st.shared::cluster.f32 [%0], %1;" :: "r"(addr), "f"(v));
}
#define CSYNC() do { \
    asm volatile("barrier.cluster.arrive.aligned;" ::: "memory"); \
    asm volatile("barrier.cluster.wait.aligned;" ::: "memory"); } while (0)

// XOR swizzle: (r, c) -> r*L + (c ^ ((r<<2) & (L-4))).
__device__ __forceinline__ void stage_w(const float* __restrict__ g, float* __restrict__ s,
                                        int R, int L, int tid, int T) {
    int total4 = (R * L) >> 2;
    for (int e4 = tid; e4 < total4; e4 += T) {
        int e = e4 << 2;
        int r = e / L;
        int c = e & (L - 1);
        float4 v = *reinterpret_cast<const float4*>(g + e);
        *reinterpret_cast<float4*>(s + r * L + (c ^ ((r << 2) & (L - 4)))) = v;
    }
}

// stage only rows [r0, r0+R) of an [*, L] matrix into the SAME smem layout slots
__device__ __forceinline__ void stage_rows_async(const float* __restrict__ g, float* __restrict__ s,
                                                 int r0, int R, int L, int tid, int T) {
    int total4 = (R * L) >> 2;
    for (int e4 = tid; e4 < total4; e4 += T) {
        int e = e4 << 2;
        int r = r0 + e / L;
        int c = e & (L - 1);
        cp_async16(s + r * L + (c ^ ((r << 2) & (L - 4))), g + r * L + c);
    }
}

// scalar gemm: acc[n] = sum_{c in [c0,c0+nc)} W[r][c]*act[n*L+c]
__device__ __forceinline__ void gemm_sc(const float* __restrict__ Wsm,
                                        const float* __restrict__ act,
                                        int r, int L, int c0, int nc, float* acc) {
#pragma unroll
    for (int n = 0; n < NCL; n++) acc[n] = 0.f;
    const int sw = (r << 2) & (L - 4);
    const float* wrow = Wsm + r * L;
#pragma unroll 4
    for (int c = c0; c < c0 + nc; c += 4) {
        float4 w = *reinterpret_cast<const float4*>(wrow + (c ^ sw));
#pragma unroll
        for (int n = 0; n < NCL; n++) {
            float4 a = *reinterpret_cast<const float4*>(act + n * L + c);
            acc[n] = fmaf(w.x, a.x, acc[n]);
            acc[n] = fmaf(w.y, a.y, acc[n]);
            acc[n] = fmaf(w.z, a.z, acc[n]);
            acc[n] = fmaf(w.w, a.w, acc[n]);
        }
    }
}

// ---------------- phase 1: iterative slot attention, 8-CTA cluster ----------------
// R14 structure; init stages ONLY the weight rows this CTA's output slice needs.

__global__ void __launch_bounds__(TPB1) __cluster_dims__(CLN, 1, 1) phase1_kernel(
    const float* __restrict__ cc0,
    const float* __restrict__ Wk, const float* __restrict__ bk,
    const float* __restrict__ Wq, const float* __restrict__ bq,
    const float* __restrict__ Wv, const float* __restrict__ bv,
    const float* __restrict__ ccg, const float* __restrict__ ccb,
    const float* __restrict__ Wih, const float* __restrict__ Whh,
    const float* __restrict__ bih, const float* __restrict__ bhh,
    const float* __restrict__ g_lng, const float* __restrict__ g_lnb,
    const float* __restrict__ W1, const float* __restrict__ b1,
    const float* __restrict__ W2, const float* __restrict__ b2)
{
    extern __shared__ float sm[];
    float* Wq_s   = sm;                 // 4096
    float* Wih_s  = Wq_s + 4096;        // 12288
    float* Whh_s  = Wih_s + 12288;      // 12288
    float* W1_s   = Whh_s + 12288;      // 8192 (Wk rows during init)
    float* W2_s   = W1_s + 8192;        // 8192 (Wv rows during init)
    float* cc_s   = W2_s + 8192;        // 640
    float* ccp_s  = cc_s + 640;         // 640
    float* kk_s   = ccp_s + 640;        // 640
    float* lnx_s  = kk_s + 640;         // 640
    float* q_s    = lnx_s + 640;        // 640
    float* VW_s   = q_s + 640;          // 1920 ([m][192])
    float* gh_s   = VW_s + 1920;        // 1920 ([n][192])
    float* hh_s   = gh_s + 1920;        // 1280 ([n][128]); aliases vv during init
    float* attn_s = hh_s + 1280;        // 112 (100 used)
    float* mv_s   = attn_s + 112;       // 32 (20 used)
    float* vv_s   = hh_s;               // alias

    const int tid  = threadIdx.x;
    const int lane = tid & 31;
    const int wid  = tid >> 5;
    uint32_t rank;
    asm("mov.u32 %0, %%cluster_ctarank;" : "=r"(rank));

    const uint32_t kk_u = smem_u32(kk_s);
    const uint32_t vv_u = smem_u32(vv_s);
    const uint32_t q_u  = smem_u32(q_s);
    const uint32_t gh_u = smem_u32(gh_s);
    const uint32_t vw_u = smem_u32(VW_s);
    const uint32_t cc_u = smem_u32(cc_s);
    const uint32_t hh_u = smem_u32(hh_s);

    // G0 async: per-CTA rows of Wih + (Wq for ranks 0-1 | Whh for ranks 2-7)
    stage_rows_async(Wih, Wih_s, rank * 24, 24, 64, tid, TPB1);
    if (rank < 2) stage_rows_async(Wq, Wq_s, rank * 32, 32, 64, tid, TPB1);
    else          stage_rows_async(Whh, Whh_s, rank * 32 - 64, 32, 64, tid, TPB1);
    asm volatile("cp.async.commit_group;\n" ::: "memory");   // G0

    // sync: per-CTA rows of Wk (ranks 0-3, into W1_s) or Wv (ranks 4-7, into W2_s); cc
    {
        const float* gsrc = (rank < 4) ? Wk : Wv;
        float* dst = (rank < 4) ? W1_s : W2_s;
        int r0 = (rank < 4) ? rank * 16 : (rank - 4) * 16;
        int total4 = (16 * 64) >> 2;
        for (int e4 = tid; e4 < total4; e4 += TPB1) {
            int e = e4 << 2;
            int r = r0 + (e >> 6);
            int c = e & 63;
            float4 v = *reinterpret_cast<const float4*>(gsrc + r * 64 + c);
            *reinterpret_cast<float4*>(dst + r * 64 + (c ^ ((r << 2) & 60))) = v;
        }
    }
    if (tid < 160) *reinterpret_cast<float4*>(cc_s + tid * 4) =
        *reinterpret_cast<const float4*>(cc0 + tid * 4);
    __syncthreads();

    // k, v : 16 rows per CTA, splitk4 -> tid<64
    if (tid < 64) {
        int rid = tid >> 2, kp = tid & 3;
        int grow = rank * 16 + rid;
        float acc[NCL];
        const float* Wm = (grow < 64) ? W1_s : W2_s;
        int row = grow & 63;
        gemm_sc(Wm, cc_s, row, 64, kp * 16, 16, acc);
#pragma unroll
        for (int n = 0; n < NCL; n++) {
            acc[n] += __shfl_xor_sync(0xffffffffu, acc[n], 1);
            acc[n] += __shfl_xor_sync(0xffffffffu, acc[n], 2);
        }
        if (kp == 0) {
            float b = (grow < 64) ? bk[row] : bv[row];
            uint32_t base_u = (grow < 64) ? kk_u : vv_u;
            float vals[NCL];
#pragma unroll
            for (int n = 0; n < NCL; n++) vals[n] = acc[n] + b;
            for (int pr = 0; pr < CLN; pr++) {
                uint32_t b0 = mapa_rank(base_u, pr);
#pragma unroll
                for (int n = 0; n < NCL; n++)
                    st_cluster_f32(b0 + (uint32_t)(n * 64 + row) * 4u, vals[n]);
            }
        }
    }
    CSYNC();   // kk, vv full in every CTA

    // G1 async: per-CTA rows of W1, W2
    stage_rows_async(W1, W1_s, rank * 16, 16, 64, tid, TPB1);
    stage_rows_async(W2, W2_s, rank * 8, 8, 128, tid, TPB1);
    asm volatile("cp.async.commit_group;\n" ::: "memory");   // G1
    asm volatile("cp.async.wait_group 1;\n" ::: "memory");   // G0 drained
    __syncthreads();

    // VW: 24 rows per CTA, splitk4 -> tid<96
    if (tid < 96) {
        int rid = tid >> 2, kp = tid & 3;
        int grow = rank * 24 + rid;
        float acc[NCL];
        gemm_sc(Wih_s, vv_s, grow, 64, kp * 16, 16, acc);
#pragma unroll
        for (int n = 0; n < NCL; n++) {
            acc[n] += __shfl_xor_sync(0xffffffffu, acc[n], 1);
            acc[n] += __shfl_xor_sync(0xffffffffu, acc[n], 2);
        }
        if (kp == 0) {
            for (int pr = 0; pr < CLN; pr++) {
                uint32_t b0 = mapa_rank(vw_u, pr);
#pragma unroll
                for (int n = 0; n < NCL; n++)
                    st_cluster_f32(b0 + (uint32_t)(n * 192 + grow) * 4u, acc[n]);
            }
        }
    }
    asm volatile("cp.async.wait_group 0;\n" ::: "memory");   // W1/W2 ready
    CSYNC();   // VW full everywhere

    for (int it = 0; it < 3; ++it) {
        ccp_s[tid] = cc_s[tid];
        if (tid < 128) ccp_s[512 + tid] = cc_s[512 + tid];
        if (wid < NCL) {
            float x0 = cc_s[wid * 64 + lane * 2];
            float x1 = cc_s[wid * 64 + lane * 2 + 1];
            float s = x0 + x1, q2 = x0 * x0 + x1 * x1;
#pragma unroll
            for (int o = 16; o; o >>= 1) {
                s  += __shfl_xor_sync(0xffffffffu, s, o);
                q2 += __shfl_xor_sync(0xffffffffu, q2, o);
            }
            if (lane == 0) {
                float m = s * (1.f / 64.f);
                mv_s[2 * wid] = m;
                mv_s[2 * wid + 1] = rsqrtf(q2 * (1.f / 64.f) - m * m + 1e-5f);
            }
        }
        __syncthreads();
        {
            int e = tid, n = e >> 6, i = e & 63;
            lnx_s[e] = (cc_s[e] - mv_s[2 * n]) * mv_s[2 * n + 1] * ccg[i] + ccb[i];
            if (tid < 128) {
                e = 512 + tid; n = e >> 6; i = e & 63;
                lnx_s[e] = (cc_s[e] - mv_s[2 * n]) * mv_s[2 * n + 1] * ccg[i] + ccb[i];
            }
        }
        __syncthreads();

        // stage A: 32 rows per CTA, splitk4 -> tid<128
        if (tid < 128) {
            int rid = tid >> 2, kp = tid & 3;
            int grow = rank * 32 + rid;
            float acc[NCL];
            if (grow < 64) gemm_sc(Wq_s, lnx_s, grow, 64, kp * 16, 16, acc);
            else           gemm_sc(Whh_s, ccp_s, grow - 64, 64, kp * 16, 16, acc);
#pragma unroll
            for (int n = 0; n < NCL; n++) {
                acc[n] += __shfl_xor_sync(0xffffffffu, acc[n], 1);
                acc[n] += __shfl_xor_sync(0xffffffffu, acc[n], 2);
            }
            if (kp == 0) {
                float vals[NCL];
                if (grow < 64) {
                    float b = bq[grow];
#pragma unroll
                    for (int n = 0; n < NCL; n++) vals[n] = acc[n] + b;
                    for (int pr = 0; pr < CLN; pr++) {
                        uint32_t b0 = mapa_rank(q_u, pr);
#pragma unroll
                        for (int n = 0; n < NCL; n++)
                            st_cluster_f32(b0 + (uint32_t)(n * 64 + grow) * 4u, vals[n]);
                    }
                } else {
                    int r = grow - 64;
                    float b = bhh[r];
#pragma unroll
                    for (int n = 0; n < NCL; n++) vals[n] = acc[n] + b;
                    for (int pr = 0; pr < CLN; pr++) {
                        uint32_t b0 = mapa_rank(gh_u, pr);
#pragma unroll
                        for (int n = 0; n < NCL; n++)
                            st_cluster_f32(b0 + (uint32_t)(n * 192 + r) * 4u, vals[n]);
                    }
                }
            }
        }
        CSYNC();

        // replicated: logits, softmax, renorm
        {
            int nm = tid >> 2; if (nm > 99) nm = 99;
            int kp = tid & 3;
            int n = nm / 10, m = nm % 10;
            float s = 0.f;
            int c0 = kp * 16;
#pragma unroll
            for (int j = 0; j < 16; j++)
                s = fmaf(kk_s[n * 64 + c0 + j], q_s[m * 64 + c0 + j], s);
            s += __shfl_xor_sync(0xffffffffu, s, 1);
            s += __shfl_xor_sync(0xffffffffu, s, 2);
            if (tid < 400 && kp == 0) attn_s[n * 10 + m] = s * 0.125f;
        }
        __syncthreads();
        if (tid < NCL) {
            int m = tid;
            float a[NCL], mx = -1e30f;
#pragma unroll
            for (int n = 0; n < NCL; n++) { a[n] = attn_s[n * 10 + m]; mx = fmaxf(mx, a[n]); }
            float ss = 0.f;
#pragma unroll
            for (int n = 0; n < NCL; n++) { a[n] = __expf(a[n] - mx); ss += a[n]; }
            float inv = 1.f / ss;
#pragma unroll
            for (int n = 0; n < NCL; n++) attn_s[n * 10 + m] = a[n] * inv + 1e-8f;
        }
        __syncthreads();
        if (tid < NCL) {
            int n = tid;
            float ss = 0.f;
#pragma unroll
            for (int m = 0; m < NCL; m++) ss += attn_s[n * 10 + m];
            float inv = 1.f / ss;
#pragma unroll
            for (int m = 0; m < NCL; m++) attn_s[n * 10 + m] *= inv;
        }
        __syncthreads();

        // GRU: 80 elements per CTA
        if (tid < 80) {
            int e = rank * 80 + tid;
            int n = e >> 6, i = e & 63;
            float gi0 = bih[i], gi1 = bih[64 + i], gi2 = bih[128 + i];
#pragma unroll
            for (int m = 0; m < NCL; m++) {
                float a = attn_s[n * 10 + m];
                const float* vw = VW_s + m * 192;
                gi0 = fmaf(a, vw[i], gi0);
                gi1 = fmaf(a, vw[64 + i], gi1);
                gi2 = fmaf(a, vw[128 + i], gi2);
            }
            float h0 = gh_s[n * 192 + i];
            float h1 = gh_s[n * 192 + 64 + i];
            float h2 = gh_s[n * 192 + 128 + i];
            float r = fast_sigmoid(gi0 + h0);
            float z = fast_sigmoid(gi1 + h1);
            float nn = fast_tanh(gi2 + r * h2);
            float v = (1.f - z) * nn + z * ccp_s[e];
            for (int pr = 0; pr < CLN; pr++)
                st_cluster_f32(mapa_rank(cc_u, pr) + (uint32_t)e * 4u, v);
        }
        CSYNC();

        // LN2 stats + lnx
        if (wid < NCL) {
            float x0 = cc_s[wid * 64 + lane * 2];
            float x1 = cc_s[wid * 64 + lane * 2 + 1];
            float s = x0 + x1, q2 = x0 * x0 + x1 * x1;
#pragma unroll
            for (int o = 16; o; o >>= 1) {
                s  += __shfl_xor_sync(0xffffffffu, s, o);
                q2 += __shfl_xor_sync(0xffffffffu, q2, o);
            }
            if (lane == 0) {
                float m = s * (1.f / 64.f);
                mv_s[2 * wid] = m;
                mv_s[2 * wid + 1] = rsqrtf(q2 * (1.f / 64.f) - m * m + 1e-5f);
            }
        }
        __syncthreads();
        {
            int e = tid, n = e >> 6, i = e & 63;
            lnx_s[e] = (cc_s[e] - mv_s[2 * n]) * mv_s[2 * n + 1] * g_lng[i] + g_lnb[i];
            if (tid < 128) {
                e = 512 + tid; n = e >> 6; i = e & 63;
                lnx_s[e] = (cc_s[e] - mv_s[2 * n]) * mv_s[2 * n + 1] * g_lng[i] + g_lnb[i];
            }
        }
        __syncthreads();

        // MLP1: 16 rows per CTA, splitk4 -> tid<64
        if (tid < 64) {
            int rid = tid >> 2, kp = tid & 3;
            int grow = rank * 16 + rid;
            float acc[NCL];
            gemm_sc(W1_s, lnx_s, grow, 64, kp * 16, 16, acc);
#pragma unroll
            for (int n = 0; n < NCL; n++) {
                acc[n] += __shfl_xor_sync(0xffffffffu, acc[n], 1);
                acc[n] += __shfl_xor_sync(0xffffffffu, acc[n], 2);
            }
            if (kp == 0) {
                float b = b1[grow];
                float vals[NCL];
#pragma unroll
                for (int n = 0; n < NCL; n++) vals[n] = fmaxf(acc[n] + b, 0.f);
                for (int pr = 0; pr < CLN; pr++) {
                    uint32_t b0 = mapa_rank(hh_u, pr);
#pragma unroll
                    for (int n = 0; n < NCL; n++)
                        st_cluster_f32(b0 + (uint32_t)(n * 128 + grow) * 4u, vals[n]);
                }
            }
        }
        CSYNC();

        // MLP2 + residual: 8 rows per CTA, splitk8 -> tid<64
        if (tid < 64) {
            int rid = tid >> 3, kp = tid & 7;
            int grow = rank * 8 + rid;
            float acc[NCL];
            gemm_sc(W2_s, hh_s, grow, 128, kp * 16, 16, acc);
#pragma unroll
            for (int n = 0; n < NCL; n++) {
                acc[n] += __shfl_xor_sync(0xffffffffu, acc[n], 1);
                acc[n] += __shfl_xor_sync(0xffffffffu, acc[n], 2);
                acc[n] += __shfl_xor_sync(0xffffffffu, acc[n], 4);
            }
            if (kp == 0) {
                float b = b2[grow];
                float vals[NCL];
#pragma unroll
                for (int n = 0; n < NCL; n++)
                    vals[n] = cc_s[n * 64 + grow] + acc[n] + b;
                for (int pr = 0; pr < CLN; pr++) {
                    uint32_t b0 = mapa_rank(cc_u, pr);
#pragma unroll
                    for (int n = 0; n < NCL; n++)
                        st_cluster_f32(b0 + (uint32_t)(n * 64 + grow) * 4u, vals[n]);
                }
            }
        }
        CSYNC();
    }

    if (rank == 0) {
        g_cc[tid] = cc_s[tid];
        if (tid < 128) g_cc[512 + tid] = cc_s[512 + tid];
    }
}

// ---------------- kernel 2: per-slot MLP + max (4096 blocks) — R6 proven (~39.8us) ----------------

__global__ void __launch_bounds__(64) slot_kernel(
    const float* __restrict__ Wa, const float* __restrict__ ba,
    const float* __restrict__ Wb, const float* __restrict__ bb,
    float* __restrict__ out)
{
    __shared__ float bufA[4096];
    __shared__ float bufB[4096];
    __shared__ float cc2[640];
    __shared__ float hsm[640];

    const int s = blockIdx.x;
    const int t = threadIdx.x;
    const float* wa = Wa + (size_t)s * 4096;
    const float* wb = Wb + (size_t)s * 4096;

#pragma unroll
    for (int k = 0; k < 16; ++k) {
        int e = (t + 64 * k) * 4;
        int r = e >> 6, c = e & 63;
        cp_async16(&bufA[r * 64 + (c ^ ((r << 2) & 60))], wa + e);
    }
    asm volatile("cp.async.commit_group;\n" ::: "memory");
#pragma unroll
    for (int k = 0; k < 16; ++k) {
        int e = (t + 64 * k) * 4;
        int r = e >> 6, c = e & 63;
        cp_async16(&bufB[r * 64 + (c ^ ((r << 2) & 60))], wb + e);
    }
    asm volatile("cp.async.commit_group;\n" ::: "memory");

    for (int e = t; e < 640; e += 64) cc2[e] = g_cc[e];

    asm volatile("cp.async.wait_group 1;\n" ::: "memory");
    __syncthreads();

    float acc[NCL];
    gemm_sc(bufA, cc2, t, 64, 0, 64, acc);
    {
        float b = ba[s * 64 + t];
#pragma unroll
        for (int n = 0; n < NCL; n++) hsm[n * 64 + t] = fmaxf(acc[n] + b, 0.f);
    }

    asm volatile("cp.async.wait_group 0;\n" ::: "memory");
    __syncthreads();

    gemm_sc(bufB, hsm, t, 64, 0, 64, acc);
    float b = bb[s * 64 + t];
    float m = -3.4e38f;
#pragma unroll
    for (int n = 0; n < NCL; n++) m = fmaxf(m, acc[n] + b);
    out[s * 64 + t] = m;
}

// ---------------- launch ----------------

extern "C" void kernel_launch(void* const* d_in, const int* in_sizes, int n_in,
                              void* d_out, int out_size) {
    const float* cc0 = (const float*)d_in[0];
    const float* Wk  = (const float*)d_in[1];
    const float* bk  = (const float*)d_in[2];
    const float* Wq  = (const float*)d_in[3];
    const float* bq  = (const float*)d_in[4];
    const float* Wv  = (const float*)d_in[5];
    const float* bv  = (const float*)d_in[6];
    const float* ccg = (const float*)d_in[7];
    const float* ccb = (const float*)d_in[8];
    const float* Wih = (const float*)d_in[9];
    const float* Whh = (const float*)d_in[10];
    const float* bih = (const float*)d_in[11];
    const float* bhh = (const float*)d_in[12];
    const float* lng = (const float*)d_in[13];
    const float* lnb = (const float*)d_in[14];
    const float* W1  = (const float*)d_in[15];
    const float* b1  = (const float*)d_in[16];
    const float* W2  = (const float*)d_in[17];
    const float* b2  = (const float*)d_in[18];
    const float* Wa  = (const float*)d_in[19];
    const float* ba  = (const float*)d_in[20];
    const float* Wb  = (const float*)d_in[21];
    const float* bb  = (const float*)d_in[22];
    float* out = (float*)d_out;

    constexpr int SMEM1 = 53520 * 4;  // 214,080 B
    cudaFuncSetAttribute(phase1_kernel, cudaFuncAttributeMaxDynamicSharedMemorySize, SMEM1);

    phase1_kernel<<<CLN, TPB1, SMEM1>>>(cc0, Wk, bk, Wq, bq, Wv, bv, ccg, ccb,
                                        Wih, Whh, bih, bhh, lng, lnb, W1, b1, W2, b2);
    slot_kernel<<<4096, 64>>>(Wa, ba, Wb, bb, out);
}